// round 10
// baseline (speedup 1.0000x reference)
#include <cuda_runtime.h>
#include <cstdint>

// MeanAggregator: out[b, :] = (1/K) * sum_k features[neigh_idx[b,k], :]
// features: [1e6, 128] fp32 (512 MB), neigh_idx: [1e5, 10] int32, out: [1e5,128] fp32.
//
// FINAL (R7 winner + micro-cleanup). DRAM-bound random gather at the
// random-512B efficiency plateau (~6.5 TB/s, DRAM ~82% active).
//
// Shape: one-shot grid, ONE WARP PER OUTPUT ROW. Lane l owns float4 chunk l
// (32 x 16B = 512B = one feature row) -> every gathered row is one fully
// coalesced 512B access. K=10 fully unrolled -> 10 independent LDG.128
// front-batched per warp (MLP=10). __launch_bounds__(256, 8) caps regs at 32
// -> 64 warps/SM (the measured concurrency sweet spot).
//
// Tested and rejected: 2 rows/warp (78.3us), persistent loop + prefetch
// (82.4us), 128-thr blocks (76.9us), L2 evict_last policy (neutral),
// ld.cg/st.cs cache paths (neutral). Traffic-reduction restructurings
// (sorted gather + scatter-accumulate, inverted index) lose to L2-atomic/RMW
// floors on paper.
//
// R10 cleanup: B = 100,000 = grid(12,500) x 8 warps exactly -> no tail check;
// 32-bit row-offset math (j*128 < 2^27) removes the 64-bit IMAD.WIDE chain.

#define D 128
#define KNEIGH 10

__global__ __launch_bounds__(256, 8) void mean_agg_kernel(
    const float* __restrict__ features,
    const int* __restrict__ neigh_idx,
    float* __restrict__ out)
{
    const int warp_global = (blockIdx.x * blockDim.x + threadIdx.x) >> 5;
    const int lane = threadIdx.x & 31;

    // Lanes 0..9 each load one neighbor index for this row, broadcast via shfl.
    int my_idx = 0;
    if (lane < KNEIGH) {
        my_idx = __ldg(neigh_idx + warp_global * KNEIGH + lane);
    }

    float4 acc = make_float4(0.f, 0.f, 0.f, 0.f);

    #pragma unroll
    for (int k = 0; k < KNEIGH; ++k) {
        unsigned j = (unsigned)__shfl_sync(0xffffffffu, my_idx, k);
        // j < 2^20, j*D < 2^27: 32-bit offset, single IMAD.
        float4 v = __ldg(reinterpret_cast<const float4*>(features + j * D) + lane);
        acc.x += v.x;
        acc.y += v.y;
        acc.z += v.z;
        acc.w += v.w;
    }

    const float inv_k = 1.0f / (float)KNEIGH;
    float4 r = make_float4(acc.x * inv_k, acc.y * inv_k, acc.z * inv_k, acc.w * inv_k);
    reinterpret_cast<float4*>(out + (long long)warp_global * D)[lane] = r;
}

extern "C" void kernel_launch(void* const* d_in, const int* in_sizes, int n_in,
                              void* d_out, int out_size)
{
    const float* features = (const float*)d_in[0];
    const int* neigh_idx  = (const int*)d_in[1];
    float* out            = (float*)d_out;

    const int B = in_sizes[1] / KNEIGH;   // 100,000
    const int warps_per_block = 256 / 32; // 8
    const int grid = (B + warps_per_block - 1) / warps_per_block; // 12,500 (exact)

    mean_agg_kernel<<<grid, 256>>>(features, neigh_idx, out);
}

// round 11
// speedup vs baseline: 1.0062x; 1.0062x over previous
#include <cuda_runtime.h>
#include <cstdint>

// MeanAggregator: out[b, :] = (1/K) * sum_k features[neigh_idx[b,k], :]
// features: [1e6, 128] fp32 (512 MB), neigh_idx: [1e5, 10] int32, out: [1e5,128] fp32.
//
// FINAL — exact R7 winner (75.9 us, DRAM 82.3% active, 6.52 TB/s = 81.5% of
// spec HBM). DRAM-bound random gather at the random-512B efficiency plateau.
//
// Shape: one-shot grid, ONE WARP PER OUTPUT ROW. Lane l owns float4 chunk l
// (32 x 16B = 512B = one feature row) -> every gathered row is one fully
// coalesced 512B access. K=10 fully unrolled -> 10 independent LDG.128
// front-batched per warp (MLP=10). 64-bit index math lets ptxas fold the row
// offset into IMAD.WIDE + 64-bit LDG addressing (R10's 32-bit rewrite added
// per-load ALU and lost 2.4 us). __launch_bounds__(256, 8) caps regs at 32
// -> 64 warps/SM, the measured concurrency sweet spot.
//
// Measured & rejected: 2 rows/warp (78.3), persistent loop+prefetch (82.4),
// 128-thr blocks (76.9), 32-bit addr math (78.3), L2 evict_last policy,
// ld.cg/st.cs (both neutral). Traffic-reducing restructurings lose to
// L2-atomic/RMW floors by model.

#define D 128
#define KNEIGH 10

__global__ __launch_bounds__(256, 8) void mean_agg_kernel(
    const float* __restrict__ features,
    const int* __restrict__ neigh_idx,
    float* __restrict__ out,
    int B)
{
    const int warp_global = (blockIdx.x * blockDim.x + threadIdx.x) >> 5;
    const int lane = threadIdx.x & 31;
    if (warp_global >= B) return;

    // Lanes 0..9 each load one neighbor index for this row, broadcast via shfl.
    int my_idx = 0;
    if (lane < KNEIGH) {
        my_idx = __ldg(neigh_idx + (long long)warp_global * KNEIGH + lane);
    }

    float4 acc = make_float4(0.f, 0.f, 0.f, 0.f);

    #pragma unroll
    for (int k = 0; k < KNEIGH; ++k) {
        long long j = __shfl_sync(0xffffffffu, my_idx, k);
        float4 v = __ldg(reinterpret_cast<const float4*>(features + j * D) + lane);
        acc.x += v.x;
        acc.y += v.y;
        acc.z += v.z;
        acc.w += v.w;
    }

    const float inv_k = 1.0f / (float)KNEIGH;
    float4 r = make_float4(acc.x * inv_k, acc.y * inv_k, acc.z * inv_k, acc.w * inv_k);
    reinterpret_cast<float4*>(out + (long long)warp_global * D)[lane] = r;
}

extern "C" void kernel_launch(void* const* d_in, const int* in_sizes, int n_in,
                              void* d_out, int out_size)
{
    const float* features = (const float*)d_in[0];
    const int* neigh_idx  = (const int*)d_in[1];
    float* out            = (float*)d_out;

    const int B = in_sizes[1] / KNEIGH;   // 100,000

    const int warps_per_block = 256 / 32; // 8
    const int grid = (B + warps_per_block - 1) / warps_per_block; // 12,500

    mean_agg_kernel<<<grid, 256>>>(features, neigh_idx, out, B);
}

// round 12
// speedup vs baseline: 1.0099x; 1.0037x over previous
#include <cuda_runtime.h>
#include <cstdint>

// MeanAggregator: out[b, :] = (1/K) * sum_k features[neigh_idx[b,k], :]
// features: [1e6, 128] fp32 (512 MB), neigh_idx: [1e5, 10] int32, out: [1e5,128] fp32.
//
// FINAL — converged kernel (best observed 75.9 us; identical-source rerun
// 77.8 us establishes +-2 us run-to-run noise, so the variant matrix below is
// settled). DRAM-bound random gather at the random-512B efficiency plateau:
// ~6.4 TB/s, DRAM ~80-82% active, ~488 MB total traffic.
//
// Shape: one-shot grid, ONE WARP PER OUTPUT ROW. Lane l owns float4 chunk l
// (32 x 16B = 512B = one feature row) -> every gathered row is one fully
// coalesced 512B access. K=10 fully unrolled -> 10 independent LDG.128
// front-batched per warp (MLP=10). 64-bit index math folds into IMAD.WIDE +
// 64-bit LDG addressing (32-bit rewrite added per-load ALU, -2.4 us).
// __launch_bounds__(256, 8) caps regs at 32 -> 64 warps/SM.
//
// Measured: 2 rows/warp 78.3 / persistent loop 82.4 / 128-thr blocks 76.9 /
// 32-bit addr 78.3 (regressions); L2 evict_last, ld.cg+st.cs (neutral —
// cache policy does not move random gathers on sm_103a). Modeled and
// rejected: segmented L2-resident passes (out-RMW adds ~459 MB), sorted
// scatter-accumulate (L2 atomic floor), v8 loads (re-enters losing shape).

#define D 128
#define KNEIGH 10

__global__ __launch_bounds__(256, 8) void mean_agg_kernel(
    const float* __restrict__ features,
    const int* __restrict__ neigh_idx,
    float* __restrict__ out,
    int B)
{
    const int warp_global = (blockIdx.x * blockDim.x + threadIdx.x) >> 5;
    const int lane = threadIdx.x & 31;
    if (warp_global >= B) return;

    // Lanes 0..9 each load one neighbor index for this row, broadcast via shfl.
    int my_idx = 0;
    if (lane < KNEIGH) {
        my_idx = __ldg(neigh_idx + (long long)warp_global * KNEIGH + lane);
    }

    float4 acc = make_float4(0.f, 0.f, 0.f, 0.f);

    #pragma unroll
    for (int k = 0; k < KNEIGH; ++k) {
        long long j = __shfl_sync(0xffffffffu, my_idx, k);
        float4 v = __ldg(reinterpret_cast<const float4*>(features + j * D) + lane);
        acc.x += v.x;
        acc.y += v.y;
        acc.z += v.z;
        acc.w += v.w;
    }

    const float inv_k = 1.0f / (float)KNEIGH;
    float4 r = make_float4(acc.x * inv_k, acc.y * inv_k, acc.z * inv_k, acc.w * inv_k);
    reinterpret_cast<float4*>(out + (long long)warp_global * D)[lane] = r;
}

extern "C" void kernel_launch(void* const* d_in, const int* in_sizes, int n_in,
                              void* d_out, int out_size)
{
    const float* features = (const float*)d_in[0];
    const int* neigh_idx  = (const int*)d_in[1];
    float* out            = (float*)d_out;

    const int B = in_sizes[1] / KNEIGH;   // 100,000

    const int warps_per_block = 256 / 32; // 8
    const int grid = (B + warps_per_block - 1) / warps_per_block; // 12,500

    mean_agg_kernel<<<grid, 256>>>(features, neigh_idx, out, B);
}